// round 2
// baseline (speedup 1.0000x reference)
#include <cuda_runtime.h>
#include <math.h>

#define NN   50000
#define FIN  256
#define FH   64
#define FOUT 32
#define EMAX 800000
#define NEG_SLOPE 0.01f

// ---------------- scratch (static device globals; no allocation) ----------------
__device__ __align__(16) float g_h[3][NN * FH];     // x @ W per branch
__device__ __align__(16) float g_e[3][NN * FH];     // layer-1 edge aggregation (pre-epilogue)
__device__ float g_dinv[3][NN];                     // deg -> rsqrt(deg)
__device__ float g_norm[3][EMAX];                   // per-edge symmetric norm (reused both layers)
__device__ __align__(16) float g_comb[NN * FH];     // attention-combined embedding
__device__ __align__(16) float g_g[3][NN * FOUT];   // combined @ W_kk
__device__ __align__(16) float g_outacc[NN * FOUT]; // summed layer-2 edge aggregation

// vectorized f32 reduction (sm_90+; PTX ISA 8.1 'red.global.add.v4.f32')
__device__ __forceinline__ void red_add_v4(float* addr, float a, float b, float c, float d) {
    asm volatile("red.global.add.v4.f32 [%0], {%1, %2, %3, %4};"
                 :: "l"(addr), "f"(a), "f"(b), "f"(c), "f"(d) : "memory");
}

// ---------------- init / zero ----------------
__global__ void k_init() {
    int stride = gridDim.x * blockDim.x;
    int i0 = blockIdx.x * blockDim.x + threadIdx.x;
    float* ef = &g_e[0][0];
    for (int i = i0; i < 3 * NN * FH; i += stride) ef[i] = 0.0f;
    for (int i = i0; i < NN * FOUT; i += stride) g_outacc[i] = 0.0f;
    float* df = &g_dinv[0][0];
    for (int i = i0; i < 3 * NN; i += stride) df[i] = 1.0f;   // self-loop weight
}

// ---------------- degree ----------------
__global__ void k_deg(const int* __restrict__ dst, const float* __restrict__ w, int E, int br) {
    int e = blockIdx.x * blockDim.x + threadIdx.x;
    if (e < E) atomicAdd(&g_dinv[br][dst[e]], w[e]);
}

__global__ void k_rsqrt() {
    int i = blockIdx.x * blockDim.x + threadIdx.x;
    float* df = &g_dinv[0][0];
    if (i < 3 * NN) df[i] = rsqrtf(df[i]);
}

__global__ void k_norm(const int* __restrict__ src, const int* __restrict__ dst,
                       const float* __restrict__ w, int E, int br) {
    int e = blockIdx.x * blockDim.x + threadIdx.x;
    if (e < E) g_norm[br][e] = g_dinv[br][src[e]] * w[e] * g_dinv[br][dst[e]];
}

// ---------------- GEMM1: [NN,256] @ [256,64] -> g_h[br] ----------------
// 64-row tile per block, 256 threads, 4x4 microtile, BK=16.
__global__ void k_gemm1(const float* __restrict__ X, const float* __restrict__ W, int br) {
    __shared__ float xs[16][68];   // transposed x tile, padded
    __shared__ float ws[16][64];
    int tid = threadIdx.x;
    int m0 = blockIdx.x * 64;
    int ty = tid >> 4, tx = tid & 15;
    float acc[4][4] = {};

    for (int k0 = 0; k0 < FIN; k0 += 16) {
        {
            int r = tid >> 2;
            int kk = (tid & 3) * 4;
            int grow = m0 + r;
            float4 v = make_float4(0.f, 0.f, 0.f, 0.f);
            if (grow < NN) v = *(const float4*)(X + (size_t)grow * FIN + k0 + kk);
            xs[kk + 0][r] = v.x; xs[kk + 1][r] = v.y; xs[kk + 2][r] = v.z; xs[kk + 3][r] = v.w;
        }
        {
            int kr = tid >> 4, c = (tid & 15) * 4;
            *(float4*)&ws[kr][c] = *(const float4*)(W + (size_t)(k0 + kr) * FH + c);
        }
        __syncthreads();
        #pragma unroll
        for (int k = 0; k < 16; k++) {
            float4 a = *(const float4*)&xs[k][ty * 4];
            float4 b = *(const float4*)&ws[k][tx * 4];
            acc[0][0] += a.x * b.x; acc[0][1] += a.x * b.y; acc[0][2] += a.x * b.z; acc[0][3] += a.x * b.w;
            acc[1][0] += a.y * b.x; acc[1][1] += a.y * b.y; acc[1][2] += a.y * b.z; acc[1][3] += a.y * b.w;
            acc[2][0] += a.z * b.x; acc[2][1] += a.z * b.y; acc[2][2] += a.z * b.z; acc[2][3] += a.z * b.w;
            acc[3][0] += a.w * b.x; acc[3][1] += a.w * b.y; acc[3][2] += a.w * b.z; acc[3][3] += a.w * b.w;
        }
        __syncthreads();
    }
    float* H = &g_h[br][0];
    #pragma unroll
    for (int i = 0; i < 4; i++) {
        int row = m0 + ty * 4 + i;
        if (row < NN) {
            float4 o = make_float4(acc[i][0], acc[i][1], acc[i][2], acc[i][3]);
            *(float4*)(H + (size_t)row * FH + tx * 4) = o;
        }
    }
}

// ---------------- layer-1 edge scatter: 16 threads/edge, one v4 RED each ----------------
__global__ void k_scat64(const int* __restrict__ src, const int* __restrict__ dst, int E, int br) {
    int t = blockIdx.x * blockDim.x + threadIdx.x;
    int e = t >> 4;
    int f = t & 15;
    if (e >= E) return;
    int s = src[e];
    int d = dst[e];
    float nv = g_norm[br][e];
    float4 hv = ((const float4*)&g_h[br][0])[(size_t)s * 16 + f];
    float* base = &g_e[br][(size_t)d * FH + f * 4];
    red_add_v4(base, nv * hv.x, nv * hv.y, nv * hv.z, nv * hv.w);
}

// ---------------- fused layer-1 epilogue + attention: warp per node ----------------
// epilogue (self-loop + bias + relu) computed in registers; relu'd e never stored.
__global__ void k_attn(const float* __restrict__ fcw, const float* __restrict__ fcb,
                       const float* __restrict__ b1, const float* __restrict__ b2,
                       const float* __restrict__ b3, float* __restrict__ out_coef) {
    int warp = (blockIdx.x * blockDim.x + threadIdx.x) >> 5;
    int lane = threadIdx.x & 31;
    if (warp >= NN) return;
    float di1 = g_dinv[0][warp]; di1 *= di1;
    float di2 = g_dinv[1][warp]; di2 *= di2;
    float di3 = g_dinv[2][warp]; di3 *= di3;
    float2 a1 = ((const float2*)&g_e[0][0])[(size_t)warp * 32 + lane];
    float2 a2 = ((const float2*)&g_e[1][0])[(size_t)warp * 32 + lane];
    float2 a3 = ((const float2*)&g_e[2][0])[(size_t)warp * 32 + lane];
    float2 h1 = ((const float2*)&g_h[0][0])[(size_t)warp * 32 + lane];
    float2 h2 = ((const float2*)&g_h[1][0])[(size_t)warp * 32 + lane];
    float2 h3 = ((const float2*)&g_h[2][0])[(size_t)warp * 32 + lane];
    float2 bb1 = ((const float2*)b1)[lane];
    float2 bb2 = ((const float2*)b2)[lane];
    float2 bb3 = ((const float2*)b3)[lane];
    float2 e1, e2, e3;
    e1.x = fmaxf(a1.x + di1 * h1.x + bb1.x, 0.f);
    e1.y = fmaxf(a1.y + di1 * h1.y + bb1.y, 0.f);
    e2.x = fmaxf(a2.x + di2 * h2.x + bb2.x, 0.f);
    e2.y = fmaxf(a2.y + di2 * h2.y + bb2.y, 0.f);
    e3.x = fmaxf(a3.x + di3 * h3.x + bb3.x, 0.f);
    e3.y = fmaxf(a3.y + di3 * h3.y + bb3.y, 0.f);
    float2 w2 = ((const float2*)fcw)[lane];
    float d1 = e1.x * w2.x + e1.y * w2.y;
    float d2 = e2.x * w2.x + e2.y * w2.y;
    float d3 = e3.x * w2.x + e3.y * w2.y;
    #pragma unroll
    for (int o = 16; o > 0; o >>= 1) {
        d1 += __shfl_xor_sync(0xffffffffu, d1, o);
        d2 += __shfl_xor_sync(0xffffffffu, d2, o);
        d3 += __shfl_xor_sync(0xffffffffu, d3, o);
    }
    float fb = fcb[0];
    float v1 = d1 + fb, v2 = d2 + fb, v3 = d3 + fb;
    v1 = v1 > 0.f ? v1 : v1 * NEG_SLOPE;
    v2 = v2 > 0.f ? v2 : v2 * NEG_SLOPE;
    v3 = v3 > 0.f ? v3 : v3 * NEG_SLOPE;
    float x1 = expf(v1), x2 = expf(v2), x3 = expf(v3);
    float inv = 1.0f / (x1 + x2 + x3);
    float c1 = x1 * inv, c2 = x2 * inv, c3 = x3 * inv;
    float2 cmb;
    cmb.x = c1 * e1.x + c2 * e2.x + c3 * e3.x;
    cmb.y = c1 * e1.y + c2 * e2.y + c3 * e3.y;
    ((float2*)g_comb)[(size_t)warp * 32 + lane] = cmb;
    if (lane == 0) {
        out_coef[warp]          = c1;
        out_coef[NN + warp]     = c2;
        out_coef[2 * NN + warp] = c3;
    }
}

// ---------------- GEMM2: [NN,64] @ [64,32] -> g_g[br] ----------------
__global__ void k_gemm2(const float* __restrict__ W2, int br) {
    __shared__ float ws[64][32];
    __shared__ float cs[32][65];
    int tid = threadIdx.x;
    int r0 = blockIdx.x * 32;
    for (int i = tid; i < 512; i += 256)
        ((float4*)ws)[i] = ((const float4*)W2)[i];
    for (int i = tid; i < 512; i += 256) {
        int row = i >> 4, c = (i & 15) * 4;
        int gr = r0 + row;
        float4 v = make_float4(0.f, 0.f, 0.f, 0.f);
        if (gr < NN) v = ((const float4*)g_comb)[(size_t)gr * 16 + (c >> 2)];
        cs[row][c] = v.x; cs[row][c + 1] = v.y; cs[row][c + 2] = v.z; cs[row][c + 3] = v.w;
    }
    __syncthreads();
    int row = tid >> 3, cg = (tid & 7) * 4;
    float4 acc = make_float4(0.f, 0.f, 0.f, 0.f);
    #pragma unroll
    for (int k = 0; k < 64; k++) {
        float a = cs[row][k];
        float4 b = *(const float4*)&ws[k][cg];
        acc.x += a * b.x; acc.y += a * b.y; acc.z += a * b.z; acc.w += a * b.w;
    }
    int gr = r0 + row;
    if (gr < NN)
        ((float4*)&g_g[br][0])[(size_t)gr * 8 + (cg >> 2)] = acc;
}

// ---------------- layer-2 edge scatter: 8 threads/edge, one v4 RED each ----------------
__global__ void k_scat32(const int* __restrict__ src, const int* __restrict__ dst, int E, int br) {
    int t = blockIdx.x * blockDim.x + threadIdx.x;
    int e = t >> 3;
    int f = t & 7;
    if (e >= E) return;
    int s = src[e];
    int d = dst[e];
    float nv = g_norm[br][e];
    float4 gv = ((const float4*)&g_g[br][0])[(size_t)s * 8 + f];
    float* base = &g_outacc[(size_t)d * FOUT + f * 4];
    red_add_v4(base, nv * gv.x, nv * gv.y, nv * gv.z, nv * gv.w);
}

// ---------------- final: self-loops + biases, write d_out ----------------
__global__ void k_final(const float* __restrict__ b11, const float* __restrict__ b22,
                        const float* __restrict__ b33, float* __restrict__ out) {
    int i = blockIdx.x * blockDim.x + threadIdx.x;
    if (i >= NN * FOUT) return;
    int node = i >> 5, f = i & 31;
    float d1 = g_dinv[0][node];
    float d2 = g_dinv[1][node];
    float d3 = g_dinv[2][node];
    float v = g_outacc[i]
            + d1 * d1 * g_g[0][i]
            + d2 * d2 * g_g[1][i]
            + d3 * d3 * g_g[2][i]
            + b11[f] + b22[f] + b33[f];
    out[i] = v;
}

// ---------------- launch ----------------
extern "C" void kernel_launch(void* const* d_in, const int* in_sizes, int n_in,
                              void* d_out, int out_size) {
    const float* x[3]  = {(const float*)d_in[0], (const float*)d_in[1], (const float*)d_in[2]};
    const int*   ei[3] = {(const int*)d_in[3], (const int*)d_in[4], (const int*)d_in[5]};
    const float* ew[3] = {(const float*)d_in[6], (const float*)d_in[7], (const float*)d_in[8]};
    const float* W1[3] = {(const float*)d_in[9], (const float*)d_in[10], (const float*)d_in[11]};
    const float* b1[3] = {(const float*)d_in[12], (const float*)d_in[13], (const float*)d_in[14]};
    const float* fcw   = (const float*)d_in[15];
    const float* fcb   = (const float*)d_in[16];
    const float* W2[3] = {(const float*)d_in[17], (const float*)d_in[18], (const float*)d_in[19]};
    const float* b2[3] = {(const float*)d_in[20], (const float*)d_in[21], (const float*)d_in[22]};
    float* out = (float*)d_out;

    int E = in_sizes[3] / 2;

    k_init<<<2048, 256>>>();

    for (int br = 0; br < 3; br++)
        k_deg<<<(E + 255) / 256, 256>>>(ei[br] + E, ew[br], E, br);

    k_rsqrt<<<(3 * NN + 255) / 256, 256>>>();

    for (int br = 0; br < 3; br++)
        k_norm<<<(E + 255) / 256, 256>>>(ei[br], ei[br] + E, ew[br], E, br);

    for (int br = 0; br < 3; br++)
        k_gemm1<<<(NN + 63) / 64, 256>>>(x[br], W1[br], br);

    for (int br = 0; br < 3; br++)
        k_scat64<<<(E * 16 + 255) / 256, 256>>>(ei[br], ei[br] + E, E, br);

    k_attn<<<(NN * 32 + 255) / 256, 256>>>(fcw, fcb, b1[0], b1[1], b1[2], out + NN * FOUT);

    for (int br = 0; br < 3; br++)
        k_gemm2<<<(NN + 31) / 32, 256>>>(W2[br], br);

    for (int br = 0; br < 3; br++)
        k_scat32<<<(E * 8 + 255) / 256, 256>>>(ei[br], ei[br] + E, E, br);

    k_final<<<(NN * FOUT + 255) / 256, 256>>>(b2[0], b2[1], b2[2], out);
}

// round 6
// speedup vs baseline: 1.1945x; 1.1945x over previous
#include <cuda_runtime.h>
#include <math.h>
#include <stdint.h>

#define NN   50000
#define FIN  256
#define FH   64
#define FOUT 32
#define EMAX 800000
#define NEG_SLOPE 0.01f

// ---------------- scratch (static device globals; no allocation) ----------------
__device__ __align__(16) float g_h[3][NN * FH];     // x @ W per branch (tf32 mma)
__device__ __align__(16) float g_e[3][NN * FH];     // layer-1 edge aggregation (pre-epilogue)
__device__ float g_dinv[3][NN];                     // deg -> rsqrt(deg)
__device__ float g_norm[3][EMAX];                   // per-edge symmetric norm (reused both layers)
__device__ __align__(16) float g_comb[NN * FH];     // attention-combined embedding
__device__ __align__(16) float g_g[3][NN * FOUT];   // combined @ W_kk
__device__ __align__(16) float g_outacc[NN * FOUT]; // summed layer-2 edge aggregation

// vectorized f32 reduction (sm_90+)
__device__ __forceinline__ void red_add_v4(float* addr, float a, float b, float c, float d) {
    asm volatile("red.global.add.v4.f32 [%0], {%1, %2, %3, %4};"
                 :: "l"(addr), "f"(a), "f"(b), "f"(c), "f"(d) : "memory");
}

// round fp32 -> tf32 (round-to-nearest-even on 10-bit mantissa), result as fp32 bits
__device__ __forceinline__ float tf32r(float v) {
    uint32_t u;
    asm("cvt.rna.tf32.f32 %0, %1;" : "=r"(u) : "f"(v));
    return __uint_as_float(u);
}

__device__ __forceinline__ void mma_tf32(float* c, const uint32_t* a, uint32_t b0, uint32_t b1) {
    asm volatile("mma.sync.aligned.m16n8k8.row.col.f32.tf32.tf32.f32 "
                 "{%0,%1,%2,%3}, {%4,%5,%6,%7}, {%8,%9}, {%0,%1,%2,%3};"
                 : "+f"(c[0]), "+f"(c[1]), "+f"(c[2]), "+f"(c[3])
                 : "r"(a[0]), "r"(a[1]), "r"(a[2]), "r"(a[3]), "r"(b0), "r"(b1));
}

// ---------------- init / zero ----------------
__global__ void k_init() {
    int stride = gridDim.x * blockDim.x;
    int i0 = blockIdx.x * blockDim.x + threadIdx.x;
    float* ef = &g_e[0][0];
    for (int i = i0; i < 3 * NN * FH; i += stride) ef[i] = 0.0f;
    for (int i = i0; i < NN * FOUT; i += stride) g_outacc[i] = 0.0f;
    float* df = &g_dinv[0][0];
    for (int i = i0; i < 3 * NN; i += stride) df[i] = 1.0f;   // self-loop weight
}

// ---------------- degree (all 3 branches, blockIdx.y = branch) ----------------
__global__ void k_deg(const int* __restrict__ d0, const int* __restrict__ d1, const int* __restrict__ d2,
                      const float* __restrict__ w0, const float* __restrict__ w1, const float* __restrict__ w2,
                      int E) {
    int br = blockIdx.y;
    const int* dst = br == 0 ? d0 : br == 1 ? d1 : d2;
    const float* w = br == 0 ? w0 : br == 1 ? w1 : w2;
    int e = blockIdx.x * blockDim.x + threadIdx.x;
    if (e < E) atomicAdd(&g_dinv[br][dst[e]], w[e]);
}

__global__ void k_rsqrt() {
    int i = blockIdx.x * blockDim.x + threadIdx.x;
    float* df = &g_dinv[0][0];
    if (i < 3 * NN) df[i] = rsqrtf(df[i]);
}

__global__ void k_norm(const int* __restrict__ s0, const int* __restrict__ s1, const int* __restrict__ s2,
                       const float* __restrict__ w0, const float* __restrict__ w1, const float* __restrict__ w2,
                       int E) {
    int br = blockIdx.y;
    const int* src = br == 0 ? s0 : br == 1 ? s1 : s2;   // src row, dst at +E
    const float* w = br == 0 ? w0 : br == 1 ? w1 : w2;
    int e = blockIdx.x * blockDim.x + threadIdx.x;
    if (e < E) g_norm[br][e] = g_dinv[br][src[e]] * w[e] * g_dinv[br][src[E + e]];
}

// ---------------- GEMM1 (tf32 mma, error-compensated): [NN,256]@[256,64] -> g_h ----------------
// Block: 256 threads (8 warps), tile 128 rows x 64 cols, BK=16.
// Each warp: 16 rows x 64 cols via m16n8k8, 8 n-tiles.
// 3 passes per mma step: Ahi*Bhi + Alo*Bhi + Ahi*Blo  (residual ~2^-22).
__global__ void k_gemm1(const float* __restrict__ X0, const float* __restrict__ X1, const float* __restrict__ X2,
                        const float* __restrict__ W0, const float* __restrict__ W1, const float* __restrict__ W2) {
    int br = blockIdx.y;
    const float* X = br == 0 ? X0 : br == 1 ? X1 : X2;
    const float* W = br == 0 ? W0 : br == 1 ? W1 : W2;

    __shared__ float xs_hi[128][20], xs_lo[128][20];   // stride 20: conflict-free A frags
    __shared__ float ws_hi[16][72], ws_lo[16][72];     // stride 72: conflict-free B frags

    int tid = threadIdx.x;
    int warp = tid >> 5, lane = tid & 31;
    int group = lane >> 2, tig = lane & 3;
    int m0 = blockIdx.x * 128;

    float c[8][4] = {};   // 8 n-tiles x 4 accumulators

    for (int k0 = 0; k0 < FIN; k0 += 16) {
        // load X tile: 128 rows x 16 k = 512 float4, 2 per thread
        #pragma unroll
        for (int i = 0; i < 2; i++) {
            int idx = tid + i * 256;        // 0..511
            int r = idx >> 2;               // 0..127
            int cc = (idx & 3) * 4;         // 0,4,8,12
            float4 v = make_float4(0.f, 0.f, 0.f, 0.f);
            if (m0 + r < NN) v = *(const float4*)(X + (size_t)(m0 + r) * FIN + k0 + cc);
            float h0 = tf32r(v.x), h1 = tf32r(v.y), h2 = tf32r(v.z), h3 = tf32r(v.w);
            xs_hi[r][cc + 0] = h0; xs_hi[r][cc + 1] = h1; xs_hi[r][cc + 2] = h2; xs_hi[r][cc + 3] = h3;
            xs_lo[r][cc + 0] = tf32r(v.x - h0); xs_lo[r][cc + 1] = tf32r(v.y - h1);
            xs_lo[r][cc + 2] = tf32r(v.z - h2); xs_lo[r][cc + 3] = tf32r(v.w - h3);
        }
        // load W tile: 16 k x 64 cols = 256 float4, 1 per thread
        {
            int kr = tid >> 4;              // 0..15
            int cc = (tid & 15) * 4;        // 0..60
            float4 v = *(const float4*)(W + (size_t)(k0 + kr) * FH + cc);
            float h0 = tf32r(v.x), h1 = tf32r(v.y), h2 = tf32r(v.z), h3 = tf32r(v.w);
            ws_hi[kr][cc + 0] = h0; ws_hi[kr][cc + 1] = h1; ws_hi[kr][cc + 2] = h2; ws_hi[kr][cc + 3] = h3;
            ws_lo[kr][cc + 0] = tf32r(v.x - h0); ws_lo[kr][cc + 1] = tf32r(v.y - h1);
            ws_lo[kr][cc + 2] = tf32r(v.z - h2); ws_lo[kr][cc + 3] = tf32r(v.w - h3);
        }
        __syncthreads();

        #pragma unroll
        for (int kk = 0; kk < 16; kk += 8) {
            int ar = warp * 16 + group;
            uint32_t a_hi[4], a_lo[4];
            a_hi[0] = __float_as_uint(xs_hi[ar][kk + tig]);
            a_hi[1] = __float_as_uint(xs_hi[ar + 8][kk + tig]);
            a_hi[2] = __float_as_uint(xs_hi[ar][kk + tig + 4]);
            a_hi[3] = __float_as_uint(xs_hi[ar + 8][kk + tig + 4]);
            a_lo[0] = __float_as_uint(xs_lo[ar][kk + tig]);
            a_lo[1] = __float_as_uint(xs_lo[ar + 8][kk + tig]);
            a_lo[2] = __float_as_uint(xs_lo[ar][kk + tig + 4]);
            a_lo[3] = __float_as_uint(xs_lo[ar + 8][kk + tig + 4]);
            #pragma unroll
            for (int nt = 0; nt < 8; nt++) {
                int n = nt * 8 + group;
                uint32_t bh0 = __float_as_uint(ws_hi[kk + tig][n]);
                uint32_t bh1 = __float_as_uint(ws_hi[kk + tig + 4][n]);
                uint32_t bl0 = __float_as_uint(ws_lo[kk + tig][n]);
                uint32_t bl1 = __float_as_uint(ws_lo[kk + tig + 4][n]);
                mma_tf32(c[nt], a_hi, bh0, bh1);
                mma_tf32(c[nt], a_lo, bh0, bh1);
                mma_tf32(c[nt], a_hi, bl0, bl1);
            }
        }
        __syncthreads();
    }

    // store: c[nt] -> rows (r0, r0+8), cols nt*8 + 2*tig (+1)
    float* H = &g_h[br][0];
    int r0 = m0 + warp * 16 + group;
    #pragma unroll
    for (int nt = 0; nt < 8; nt++) {
        int col = nt * 8 + tig * 2;
        if (r0 < NN)     *(float2*)(H + (size_t)r0 * FH + col)       = make_float2(c[nt][0], c[nt][1]);
        if (r0 + 8 < NN) *(float2*)(H + (size_t)(r0 + 8) * FH + col) = make_float2(c[nt][2], c[nt][3]);
    }
}

// ---------------- layer-1 edge scatter: 16 threads/edge, one v4 RED each ----------------
__global__ void k_scat64(const int* __restrict__ s0, const int* __restrict__ s1, const int* __restrict__ s2,
                         int E) {
    int br = blockIdx.y;
    const int* ei = br == 0 ? s0 : br == 1 ? s1 : s2;
    int t = blockIdx.x * blockDim.x + threadIdx.x;
    int e = t >> 4;
    int f = t & 15;
    if (e >= E) return;
    int s = ei[e];
    int d = ei[E + e];
    float nv = g_norm[br][e];
    float4 hv = ((const float4*)&g_h[br][0])[(size_t)s * 16 + f];
    float* base = &g_e[br][(size_t)d * FH + f * 4];
    red_add_v4(base, nv * hv.x, nv * hv.y, nv * hv.z, nv * hv.w);
}

// ---------------- fused layer-1 epilogue + attention: warp per node ----------------
__global__ void k_attn(const float* __restrict__ fcw, const float* __restrict__ fcb,
                       const float* __restrict__ b1, const float* __restrict__ b2,
                       const float* __restrict__ b3, float* __restrict__ out_coef) {
    int warp = (blockIdx.x * blockDim.x + threadIdx.x) >> 5;
    int lane = threadIdx.x & 31;
    if (warp >= NN) return;
    float di1 = g_dinv[0][warp]; di1 *= di1;
    float di2 = g_dinv[1][warp]; di2 *= di2;
    float di3 = g_dinv[2][warp]; di3 *= di3;
    float2 a1 = ((const float2*)&g_e[0][0])[(size_t)warp * 32 + lane];
    float2 a2 = ((const float2*)&g_e[1][0])[(size_t)warp * 32 + lane];
    float2 a3 = ((const float2*)&g_e[2][0])[(size_t)warp * 32 + lane];
    float2 h1 = ((const float2*)&g_h[0][0])[(size_t)warp * 32 + lane];
    float2 h2 = ((const float2*)&g_h[1][0])[(size_t)warp * 32 + lane];
    float2 h3 = ((const float2*)&g_h[2][0])[(size_t)warp * 32 + lane];
    float2 bb1 = ((const float2*)b1)[lane];
    float2 bb2 = ((const float2*)b2)[lane];
    float2 bb3 = ((const float2*)b3)[lane];
    float2 e1, e2, e3;
    e1.x = fmaxf(a1.x + di1 * h1.x + bb1.x, 0.f);
    e1.y = fmaxf(a1.y + di1 * h1.y + bb1.y, 0.f);
    e2.x = fmaxf(a2.x + di2 * h2.x + bb2.x, 0.f);
    e2.y = fmaxf(a2.y + di2 * h2.y + bb2.y, 0.f);
    e3.x = fmaxf(a3.x + di3 * h3.x + bb3.x, 0.f);
    e3.y = fmaxf(a3.y + di3 * h3.y + bb3.y, 0.f);
    float2 w2 = ((const float2*)fcw)[lane];
    float d1 = e1.x * w2.x + e1.y * w2.y;
    float d2 = e2.x * w2.x + e2.y * w2.y;
    float d3 = e3.x * w2.x + e3.y * w2.y;
    #pragma unroll
    for (int o = 16; o > 0; o >>= 1) {
        d1 += __shfl_xor_sync(0xffffffffu, d1, o);
        d2 += __shfl_xor_sync(0xffffffffu, d2, o);
        d3 += __shfl_xor_sync(0xffffffffu, d3, o);
    }
    float fb = fcb[0];
    float v1 = d1 + fb, v2 = d2 + fb, v3 = d3 + fb;
    v1 = v1 > 0.f ? v1 : v1 * NEG_SLOPE;
    v2 = v2 > 0.f ? v2 : v2 * NEG_SLOPE;
    v3 = v3 > 0.f ? v3 : v3 * NEG_SLOPE;
    float x1 = expf(v1), x2 = expf(v2), x3 = expf(v3);
    float inv = 1.0f / (x1 + x2 + x3);
    float c1 = x1 * inv, c2 = x2 * inv, c3 = x3 * inv;
    float2 cmb;
    cmb.x = c1 * e1.x + c2 * e2.x + c3 * e3.x;
    cmb.y = c1 * e1.y + c2 * e2.y + c3 * e3.y;
    ((float2*)g_comb)[(size_t)warp * 32 + lane] = cmb;
    if (lane == 0) {
        out_coef[warp]          = c1;
        out_coef[NN + warp]     = c2;
        out_coef[2 * NN + warp] = c3;
    }
}

// ---------------- GEMM2: [NN,64] @ [64,32] -> g_g[br] (fp32, tiny) ----------------
__global__ void k_gemm2(const float* __restrict__ Wa, const float* __restrict__ Wb,
                        const float* __restrict__ Wc) {
    int br = blockIdx.y;
    const float* W2 = br == 0 ? Wa : br == 1 ? Wb : Wc;
    __shared__ float ws[64][32];
    __shared__ float cs[32][65];
    int tid = threadIdx.x;
    int r0 = blockIdx.x * 32;
    for (int i = tid; i < 512; i += 256)
        ((float4*)ws)[i] = ((const float4*)W2)[i];
    for (int i = tid; i < 512; i += 256) {
        int row = i >> 4, c = (i & 15) * 4;
        int gr = r0 + row;
        float4 v = make_float4(0.f, 0.f, 0.f, 0.f);
        if (gr < NN) v = ((const float4*)g_comb)[(size_t)gr * 16 + (c >> 2)];
        cs[row][c] = v.x; cs[row][c + 1] = v.y; cs[row][c + 2] = v.z; cs[row][c + 3] = v.w;
    }
    __syncthreads();
    int row = tid >> 3, cg = (tid & 7) * 4;
    float4 acc = make_float4(0.f, 0.f, 0.f, 0.f);
    #pragma unroll
    for (int k = 0; k < 64; k++) {
        float a = cs[row][k];
        float4 b = *(const float4*)&ws[k][cg];
        acc.x += a * b.x; acc.y += a * b.y; acc.z += a * b.z; acc.w += a * b.w;
    }
    int gr = r0 + row;
    if (gr < NN)
        ((float4*)&g_g[br][0])[(size_t)gr * 8 + (cg >> 2)] = acc;
}

// ---------------- layer-2 edge scatter: 8 threads/edge, one v4 RED each ----------------
__global__ void k_scat32(const int* __restrict__ s0, const int* __restrict__ s1, const int* __restrict__ s2,
                         int E) {
    int br = blockIdx.y;
    const int* ei = br == 0 ? s0 : br == 1 ? s1 : s2;
    int t = blockIdx.x * blockDim.x + threadIdx.x;
    int e = t >> 3;
    int f = t & 7;
    if (e >= E) return;
    int s = ei[e];
    int d = ei[E + e];
    float nv = g_norm[br][e];
    float4 gv = ((const float4*)&g_g[br][0])[(size_t)s * 8 + f];
    float* base = &g_outacc[(size_t)d * FOUT + f * 4];
    red_add_v4(base, nv * gv.x, nv * gv.y, nv * gv.z, nv * gv.w);
}

// ---------------- final: self-loops + biases, write d_out ----------------
__global__ void k_final(const float* __restrict__ b11, const float* __restrict__ b22,
                        const float* __restrict__ b33, float* __restrict__ out) {
    int i = blockIdx.x * blockDim.x + threadIdx.x;
    if (i >= NN * FOUT) return;
    int node = i >> 5, f = i & 31;
    float d1 = g_dinv[0][node];
    float d2 = g_dinv[1][node];
    float d3 = g_dinv[2][node];
    float v = g_outacc[i]
            + d1 * d1 * g_g[0][i]
            + d2 * d2 * g_g[1][i]
            + d3 * d3 * g_g[2][i]
            + b11[f] + b22[f] + b33[f];
    out[i] = v;
}

// ---------------- launch ----------------
extern "C" void kernel_launch(void* const* d_in, const int* in_sizes, int n_in,
                              void* d_out, int out_size) {
    const float* x[3]  = {(const float*)d_in[0], (const float*)d_in[1], (const float*)d_in[2]};
    const int*   ei[3] = {(const int*)d_in[3], (const int*)d_in[4], (const int*)d_in[5]};
    const float* ew[3] = {(const float*)d_in[6], (const float*)d_in[7], (const float*)d_in[8]};
    const float* W1[3] = {(const float*)d_in[9], (const float*)d_in[10], (const float*)d_in[11]};
    const float* b1[3] = {(const float*)d_in[12], (const float*)d_in[13], (const float*)d_in[14]};
    const float* fcw   = (const float*)d_in[15];
    const float* fcb   = (const float*)d_in[16];
    const float* W2[3] = {(const float*)d_in[17], (const float*)d_in[18], (const float*)d_in[19]};
    const float* b2[3] = {(const float*)d_in[20], (const float*)d_in[21], (const float*)d_in[22]};
    float* out = (float*)d_out;

    int E = in_sizes[3] / 2;

    k_init<<<2048, 256>>>();

    {   dim3 g((E + 255) / 256, 3);
        k_deg<<<g, 256>>>(ei[0] + E, ei[1] + E, ei[2] + E, ew[0], ew[1], ew[2], E); }

    k_rsqrt<<<(3 * NN + 255) / 256, 256>>>();

    {   dim3 g((E + 255) / 256, 3);
        k_norm<<<g, 256>>>(ei[0], ei[1], ei[2], ew[0], ew[1], ew[2], E); }

    {   dim3 g((NN + 127) / 128, 3);
        k_gemm1<<<g, 256>>>(x[0], x[1], x[2], W1[0], W1[1], W1[2]); }

    {   dim3 g((E * 16 + 255) / 256, 3);
        k_scat64<<<g, 256>>>(ei[0], ei[1], ei[2], E); }

    k_attn<<<(NN * 32 + 255) / 256, 256>>>(fcw, fcb, b1[0], b1[1], b1[2], out + NN * FOUT);

    {   dim3 g((NN + 31) / 32, 3);
        k_gemm2<<<g, 256>>>(W2[0], W2[1], W2[2]); }

    {   dim3 g((E * 8 + 255) / 256, 3);
        k_scat32<<<g, 256>>>(ei[0], ei[1], ei[2], E); }

    k_final<<<(NN * FOUT + 255) / 256, 256>>>(b2[0], b2[1], b2[2], out);
}